// round 1
// baseline (speedup 1.0000x reference)
#include <cuda_runtime.h>
#include <cuda_bf16.h>

// Problem constants (fixed by the reference implementation)
#define BATCH   16384
#define DIM     128
#define C_MAX   10
#define K_NEG   5
#define NWORDS  (C_MAX + K_NEG)

// Scratch accumulators (no cudaMalloc allowed) — pos_sum, neg_sum
__device__ double g_acc[2];

__device__ __forceinline__ float log_sigmoid(float x) {
    // Numerically stable: logsigmoid(x) = min(x,0) - log1p(exp(-|x|))
    return fminf(x, 0.0f) - log1pf(__expf(-fabsf(x)));
}

__global__ void sg_zero_kernel() {
    if (threadIdx.x < 2) g_acc[threadIdx.x] = 0.0;
}

__global__ __launch_bounds__(256, 8)
void sg_main_kernel(const int*   __restrict__ tgt,
                    const int*   __restrict__ ctx,
                    const int*   __restrict__ lens,
                    const int*   __restrict__ neg,
                    const float* __restrict__ in_emb,
                    const float* __restrict__ out_emb,
                    int batch)
{
    const int warp_global = (blockIdx.x * blockDim.x + threadIdx.x) >> 5;
    const int lane        = threadIdx.x & 31;
    const int warp_local  = threadIdx.x >> 5;

    __shared__ double s_pos[8];
    __shared__ double s_neg[8];

    double pos_per = 0.0, neg_per = 0.0;

    if (warp_global < batch) {
        const int b = warp_global;

        // Target row: one float4 per lane (512B coalesced)
        const int t_idx = __ldg(&tgt[b]);
        const float4 t = __ldg(((const float4*)(in_emb + (size_t)t_idx * DIM)) + lane);

        const int len = __ldg(&lens[b]);

        // Gather all 15 rows' partial dots, fully unrolled so ptxas
        // front-batches the LDG.128s (MLP ~15 hides DRAM/L2 latency).
        float sc[NWORDS];
        #pragma unroll
        for (int c = 0; c < C_MAX; ++c) {
            const int w = __ldg(&ctx[b * C_MAX + c]);
            const float4 v = __ldg(((const float4*)(out_emb + (size_t)w * DIM)) + lane);
            sc[c] = t.x * v.x + t.y * v.y + t.z * v.z + t.w * v.w;
        }
        #pragma unroll
        for (int k = 0; k < K_NEG; ++k) {
            const int w = __ldg(&neg[b * K_NEG + k]);
            const float4 v = __ldg(((const float4*)(out_emb + (size_t)w * DIM)) + lane);
            sc[C_MAX + k] = t.x * v.x + t.y * v.y + t.z * v.z + t.w * v.w;
        }

        // Butterfly-reduce all 15 dot products across the warp.
        #pragma unroll
        for (int i = 0; i < NWORDS; ++i) {
            #pragma unroll
            for (int off = 16; off > 0; off >>= 1)
                sc[i] += __shfl_xor_sync(0xffffffffu, sc[i], off);
        }

        if (len > 0) {
            float ps = 0.0f;
            #pragma unroll
            for (int c = 0; c < C_MAX; ++c)
                if (c < len) ps += log_sigmoid(sc[c]);
            pos_per = -(double)ps / (double)len;

            float ns = 0.0f;
            #pragma unroll
            for (int k = 0; k < K_NEG; ++k)
                ns += log_sigmoid(-sc[C_MAX + k]);
            neg_per = -(double)ns / (double)K_NEG;
        }
    }

    if (lane == 0) {
        s_pos[warp_local] = pos_per;
        s_neg[warp_local] = neg_per;
    }
    __syncthreads();

    if (threadIdx.x == 0) {
        double p = 0.0, n = 0.0;
        #pragma unroll
        for (int i = 0; i < 8; ++i) { p += s_pos[i]; n += s_neg[i]; }
        atomicAdd(&g_acc[0], p);
        atomicAdd(&g_acc[1], n);
    }
}

__global__ void sg_finalize_kernel(float* __restrict__ out, int batch) {
    if (threadIdx.x == 0) {
        out[0] = (float)(g_acc[0] / (double)batch);
        out[1] = (float)(g_acc[1] / (double)batch);
    }
}

extern "C" void kernel_launch(void* const* d_in, const int* in_sizes, int n_in,
                              void* d_out, int out_size)
{
    const int*   tgt     = (const int*)  d_in[0];  // (B,)
    const int*   ctx     = (const int*)  d_in[1];  // (B, C_MAX)
    const int*   lens    = (const int*)  d_in[2];  // (B,)
    const int*   neg     = (const int*)  d_in[3];  // (B, K_NEG)
    const float* in_emb  = (const float*)d_in[4];  // (VOCAB, DIM)
    const float* out_emb = (const float*)d_in[5];  // (VOCAB, DIM)
    float*       out     = (float*)d_out;

    const int batch = in_sizes[0];                 // 16384

    const int threads = 256;                       // 8 warps/block
    const int warps   = batch;
    const int blocks  = (warps * 32 + threads - 1) / threads;

    sg_zero_kernel<<<1, 32>>>();
    sg_main_kernel<<<blocks, threads>>>(tgt, ctx, lens, neg, in_emb, out_emb, batch);
    sg_finalize_kernel<<<1, 32>>>(out, batch);
}